// round 9
// baseline (speedup 1.0000x reference)
#include <cuda_runtime.h>
#include <cuda_bf16.h>
#include <cuda_fp16.h>
#include <stdint.h>
#include <math.h>

#define NMAX 50048

__device__ float g_ws[NMAX];
__device__ float g_wd[NMAX];
__device__ float g_sum;

__global__ void zero_kernel() { g_sum = 0.f; }
__global__ void finalize_kernel(float* out0, float invE) { *out0 = 1.f - g_sum * invE; }

__device__ __forceinline__ uint32_t smem_u32(const void* p) {
    uint32_t a;
    asm("{ .reg .u64 t; cvta.to.shared.u64 t, %1; cvt.u32.u64 %0, t; }" : "=r"(a) : "l"(p));
    return a;
}

__device__ __forceinline__ void ldsm4(uint32_t* r, uint32_t addr) {
    asm volatile("ldmatrix.sync.aligned.m8n8.x4.shared.b16 {%0,%1,%2,%3}, [%4];"
        : "=r"(r[0]), "=r"(r[1]), "=r"(r[2]), "=r"(r[3]) : "r"(addr));
}

__device__ __forceinline__ void mma_f16(float* c, const uint32_t* a, uint32_t b0, uint32_t b1) {
    asm volatile(
        "mma.sync.aligned.m16n8k16.row.col.f32.f16.f16.f32 "
        "{%0,%1,%2,%3}, {%4,%5,%6,%7}, {%8,%9}, {%0,%1,%2,%3};\n"
        : "+f"(c[0]), "+f"(c[1]), "+f"(c[2]), "+f"(c[3])
        : "r"(a[0]), "r"(a[1]), "r"(a[2]), "r"(a[3]), "r"(b0), "r"(b1));
}

// -------- single-pass fp16 k-step (used by edge and node) --------
__device__ __forceinline__ void k_step1(float (&c)[2][4][4],
    uint32_t aHi, uint32_t bHi, int bNpStride)
{
    uint32_t ah[2][4], bh[2][4];
    ldsm4(ah[0], aHi);  ldsm4(ah[1], aHi + 4352);
    ldsm4(bh[0], bHi);  ldsm4(bh[1], bHi + bNpStride);
    #pragma unroll
    for (int mt = 0; mt < 2; ++mt)
        #pragma unroll
        for (int np = 0; np < 2; ++np)
            #pragma unroll
            for (int s = 0; s < 2; ++s)
                mma_f16(c[mt][np * 2 + s], ah[mt], bh[np][2 * s], bh[np][2 * s + 1]);
}

// ---------------- smem layouts ----------------
// Edge (256 thr, M=64, 3 CTAs/SM)
#define E_BT  0
#define E_A   34816
#define E_B1  69632
#define E_W2  70144
#define E_RED 70656
#define EDGE_SMEM 72704

// Node (512 thr, M=128, single-pass fp16 B)
#define N_BT  0
#define N_A   67584
#define N_B1  102400
#define N_W2  102912
#define N_RED 103424
#define NODE_SMEM 104960

// ======================= NODE MLPs (fp16 single-pass) =======================
__global__ void __launch_bounds__(512, 1)
node_tc(const float* __restrict__ X, int N,
        const float* __restrict__ Ws1, const float* __restrict__ bs1,
        const float* __restrict__ ws2, const float* __restrict__ bs2,
        const float* __restrict__ Wd1, const float* __restrict__ bd1,
        const float* __restrict__ wd2, const float* __restrict__ bd2)
{
    extern __shared__ char smem[];
    const uint32_t sb = smem_u32(smem);
    const int tid = threadIdx.x;
    const int wid = tid >> 5, lane = tid & 31;
    const int warp_m = (wid >> 2) * 32, warp_n = (wid & 3) * 32;
    const int nwid = wid & 3;

    const float* W1  = blockIdx.y ? Wd1 : Ws1;
    const float* b1g = blockIdx.y ? bd1 : bs1;
    const float* w2g = blockIdx.y ? wd2 : ws2;
    const float* b2g = blockIdx.y ? bd2 : bs2;
    float* outp = blockIdx.y ? g_wd : g_ws;

    float* sB1 = (float*)(smem + N_B1);
    float* sW2 = (float*)(smem + N_W2);
    float* sRed = (float*)(smem + N_RED);

    // Bt[n][k] fp16 (hi only), stride 528. W1 is [K=256][N=128].
    for (int idx = tid; idx < 256 * 128; idx += 512) {
        int n = idx & 127, k = idx >> 7;
        *(__half*)(smem + N_BT + n * 528 + k * 2) = __float2half_rn(W1[idx]);
    }
    if (tid < 128) { sB1[tid] = b1g[tid]; sW2[tid] = w2g[tid]; }
    const float b2v = b2g[0];
    __syncthreads();

    const uint32_t aLaneOff = (uint32_t)((warp_m + (lane & 15)) * 272 + (lane >> 4) * 16);
    const uint32_t bLaneRow = (uint32_t)(warp_n + (lane & 7) + ((lane >> 4) << 3));
    const uint32_t bLaneOff = bLaneRow * 528 + (((uint32_t)lane >> 3) & 1) * 16;

    const int numTiles = (N + 127) >> 7;
    for (int tile = blockIdx.x; tile < numTiles; tile += gridDim.x) {
        float c[2][4][4];
        #pragma unroll
        for (int i = 0; i < 2; i++)
            #pragma unroll
            for (int j = 0; j < 4; j++)
                #pragma unroll
                for (int q = 0; q < 4; q++) c[i][j][q] = 0.f;

        int row = tile * 128 + (tid >> 2);
        if (row >= N) row = N - 1;
        const float4* xp = (const float4*)(X + (size_t)row * 256);
        const int q = tid & 3;
        const int myrow = tid >> 2;

        for (int kc = 0; kc < 2; ++kc) {
            __syncthreads();
            #pragma unroll
            for (int i = 0; i < 8; ++i) {
                float4 v = xp[kc * 32 + q * 8 + i];
                __half2 h0 = __floats2half2_rn(v.x, v.y);
                __half2 h1 = __floats2half2_rn(v.z, v.w);
                int byte = myrow * 272 + (q * 32 + i * 4) * 2;
                *(uint2*)(smem + N_A + byte) = make_uint2(*(uint32_t*)&h0, *(uint32_t*)&h1);
            }
            __syncthreads();
            const uint32_t aHi = sb + N_A + aLaneOff;
            const uint32_t bHi = sb + N_BT + bLaneOff + kc * 256;
            #pragma unroll
            for (int kt = 0; kt < 8; ++kt)
                k_step1(c, aHi + kt * 32, bHi + kt * 32, 16 * 528);
        }

        float part[2][2] = {{0.f, 0.f}, {0.f, 0.f}};
        #pragma unroll
        for (int mt = 0; mt < 2; ++mt)
            #pragma unroll
            for (int nt = 0; nt < 4; ++nt) {
                int n0 = warp_n + nt * 8 + (lane & 3) * 2;
                float b1a = sB1[n0], b1b = sB1[n0 + 1];
                float w2a = sW2[n0], w2b = sW2[n0 + 1];
                #pragma unroll
                for (int half = 0; half < 2; ++half) {
                    float h0 = c[mt][nt][half * 2] + b1a;     h0 = h0 > 0.f ? h0 : 0.01f * h0;
                    float h1 = c[mt][nt][half * 2 + 1] + b1b; h1 = h1 > 0.f ? h1 : 0.01f * h1;
                    part[mt][half] += h0 * w2a + h1 * w2b;
                }
            }
        #pragma unroll
        for (int mt = 0; mt < 2; ++mt)
            #pragma unroll
            for (int half = 0; half < 2; ++half) {
                part[mt][half] += __shfl_xor_sync(0xFFFFFFFFu, part[mt][half], 1);
                part[mt][half] += __shfl_xor_sync(0xFFFFFFFFu, part[mt][half], 2);
            }
        if (nwid && (lane & 3) == 0) {
            #pragma unroll
            for (int mt = 0; mt < 2; ++mt)
                #pragma unroll
                for (int half = 0; half < 2; ++half) {
                    int m = warp_m + mt * 16 + half * 8 + (lane >> 2);
                    sRed[(nwid - 1) * 128 + m] = part[mt][half];
                }
        }
        __syncthreads();
        if (nwid == 0 && (lane & 3) == 0) {
            #pragma unroll
            for (int mt = 0; mt < 2; ++mt)
                #pragma unroll
                for (int half = 0; half < 2; ++half) {
                    int m = warp_m + mt * 16 + half * 8 + (lane >> 2);
                    int nidx = tile * 128 + m;
                    if (nidx < N)
                        outp[nidx] = part[mt][half] + sRed[m] + sRed[128 + m] + sRed[256 + m] + b2v;
                }
        }
        __syncthreads();
    }
}

// ======================= EDGE MLP (fp16 single-pass, 3 CTAs/SM) =======================
__global__ void __launch_bounds__(256, 3)
edge_tc(const float* __restrict__ X, int E,
        const float* __restrict__ W1, const float* __restrict__ b1g,
        const float* __restrict__ w2g, const float* __restrict__ b2g,
        const float* __restrict__ noise, const int* __restrict__ src,
        const int* __restrict__ dst, float* __restrict__ aug)
{
    extern __shared__ char smem[];
    const uint32_t sb = smem_u32(smem);
    const int tid = threadIdx.x;
    const int wid = tid >> 5, lane = tid & 31;
    const int warp_m = (wid >> 2) * 32, warp_n = (wid & 3) * 32;
    const int nwid = wid & 3;
    const bool owner = (nwid == 0) && ((lane & 3) == 0);

    float* sB1 = (float*)(smem + E_B1);
    float* sW2 = (float*)(smem + E_W2);
    float* sRed = (float*)(smem + E_RED);

    // Bt[n][k] fp16 (hi only), stride 272. W1 is [K=128][N=128].
    for (int idx = tid; idx < 128 * 128; idx += 256) {
        int n = idx & 127, k = idx >> 7;
        *(__half*)(smem + E_BT + n * 272 + k * 2) = __float2half_rn(W1[idx]);
    }
    if (tid < 128) { sB1[tid] = b1g[tid]; sW2[tid] = w2g[tid]; }
    const float b2v = b2g[0];
    __syncthreads();

    const uint32_t aLaneOff = (uint32_t)((warp_m + (lane & 15)) * 272 + (lane >> 4) * 16);
    const uint32_t bLaneRow = (uint32_t)(warp_n + (lane & 7) + ((lane >> 4) << 3));
    const uint32_t bLaneOff = bLaneRow * 272 + (((uint32_t)lane >> 3) & 1) * 16;
    const uint32_t bHi = sb + E_BT + bLaneOff;

    const int numTiles = (E + 63) >> 6;   // M=64 tiles
    float localSum = 0.f;

    const int q = tid & 3;
    const int myrow = tid >> 2;           // 0..63

    uint32_t st[16];                       // prefetched, already fp16 (half2)
    int tile = blockIdx.x;
    bool have = tile < numTiles;
    if (have) {
        int row = tile * 64 + myrow;
        if (row >= E) row = E - 1;
        const float4* xp = (const float4*)(X + (size_t)row * 128);
        #pragma unroll
        for (int i = 0; i < 8; ++i) {
            float4 v = xp[q * 8 + i];
            __half2 h0 = __floats2half2_rn(v.x, v.y);
            __half2 h1 = __floats2half2_rn(v.z, v.w);
            st[2 * i] = *(uint32_t*)&h0;  st[2 * i + 1] = *(uint32_t*)&h1;
        }
    }

    int b = 0;
    while (have) {
        // prefetch epilogue operands for THIS tile (hidden under MMA)
        int   eIdx[4];
        float gw[4], nz[4];
        if (owner) {
            #pragma unroll
            for (int j = 0; j < 4; ++j) {
                int m = warp_m + (j >> 1) * 16 + (j & 1) * 8 + (lane >> 2);
                int e = tile * 64 + m;
                if (e < E) {
                    eIdx[j] = e;
                    int s = __ldg(&src[e]), d = __ldg(&dst[e]);
                    nz[j] = __ldg(&noise[e]);
                    gw[j] = g_ws[s] + g_wd[d];
                } else { eIdx[j] = -1; gw[j] = 0.f; nz[j] = 0.5f; }
            }
        }

        // store stash into A buffer b (4x STS.128) — short critical section
        {
            char* AH = smem + E_A + b * 17408;
            #pragma unroll
            for (int i = 0; i < 4; ++i) {
                int byte = myrow * 272 + (q * 64 + i * 16);
                *(uint4*)(AH + byte) = make_uint4(st[4 * i], st[4 * i + 1], st[4 * i + 2], st[4 * i + 3]);
            }
        }
        __syncthreads();   // sync1: A buf b ready

        // prefetch next X tile (LDG in flight during MMA), convert on arrival
        int nxt = tile + gridDim.x;
        bool haveN = nxt < numTiles;
        if (haveN) {
            int row = nxt * 64 + myrow;
            if (row >= E) row = E - 1;
            const float4* xp = (const float4*)(X + (size_t)row * 128);
            #pragma unroll
            for (int i = 0; i < 8; ++i) {
                float4 v = xp[q * 8 + i];
                __half2 h0 = __floats2half2_rn(v.x, v.y);
                __half2 h1 = __floats2half2_rn(v.z, v.w);
                st[2 * i] = *(uint32_t*)&h0;  st[2 * i + 1] = *(uint32_t*)&h1;
            }
        }

        float c[2][4][4];
        #pragma unroll
        for (int i = 0; i < 2; i++)
            #pragma unroll
            for (int j = 0; j < 4; j++)
                #pragma unroll
                for (int qq = 0; qq < 4; qq++) c[i][j][qq] = 0.f;

        const uint32_t aHi = sb + E_A + b * 17408 + aLaneOff;
        #pragma unroll
        for (int kt = 0; kt < 8; ++kt)
            k_step1(c, aHi + kt * 32, bHi + kt * 32, 16 * 272);

        // epilogue
        float part[2][2] = {{0.f, 0.f}, {0.f, 0.f}};
        #pragma unroll
        for (int mt = 0; mt < 2; ++mt)
            #pragma unroll
            for (int nt = 0; nt < 4; ++nt) {
                int n0 = warp_n + nt * 8 + (lane & 3) * 2;
                float b1a = sB1[n0], b1b = sB1[n0 + 1];
                float w2a = sW2[n0], w2b = sW2[n0 + 1];
                #pragma unroll
                for (int half = 0; half < 2; ++half) {
                    float h0 = c[mt][nt][half * 2] + b1a;     h0 = h0 > 0.f ? h0 : 0.01f * h0;
                    float h1 = c[mt][nt][half * 2 + 1] + b1b; h1 = h1 > 0.f ? h1 : 0.01f * h1;
                    part[mt][half] += h0 * w2a + h1 * w2b;
                }
            }
        #pragma unroll
        for (int mt = 0; mt < 2; ++mt)
            #pragma unroll
            for (int half = 0; half < 2; ++half) {
                part[mt][half] += __shfl_xor_sync(0xFFFFFFFFu, part[mt][half], 1);
                part[mt][half] += __shfl_xor_sync(0xFFFFFFFFu, part[mt][half], 2);
            }

        float* sRedB = sRed + (b ? 192 : 0);
        if (nwid && (lane & 3) == 0) {
            #pragma unroll
            for (int mt = 0; mt < 2; ++mt)
                #pragma unroll
                for (int half = 0; half < 2; ++half) {
                    int m = warp_m + mt * 16 + half * 8 + (lane >> 2);
                    sRedB[(nwid - 1) * 64 + m] = part[mt][half];
                }
        }
        __syncthreads();   // sync2: sRed buf b ready
        if (owner) {
            #pragma unroll
            for (int j = 0; j < 4; ++j) {
                int mt = j >> 1, half = j & 1;
                int m = warp_m + mt * 16 + half * 8 + (lane >> 2);
                if (eIdx[j] >= 0) {
                    float weight = part[mt][half] + sRedB[m] + sRedB[64 + m] + sRedB[128 + m]
                                 + b2v + gw[j];
                    float u = nz[j];
                    float eps = fmaf(2e-4f - 1.f, u, 1.f - 1e-4f);
                    float gate = (logf(eps) - log1pf(-eps) + weight) * 2.f;
                    float a = 1.f / (1.f + expf(-gate));
                    aug[eIdx[j]] = a;
                    localSum += a;
                }
            }
        }

        tile = nxt;
        have = haveN;
        b ^= 1;
    }

    #pragma unroll
    for (int o = 16; o > 0; o >>= 1)
        localSum += __shfl_xor_sync(0xFFFFFFFFu, localSum, o);
    __shared__ float sPart[8];
    if (lane == 0) sPart[wid] = localSum;
    __syncthreads();
    if (tid == 0) {
        float s = 0.f;
        #pragma unroll
        for (int i = 0; i < 8; i++) s += sPart[i];
        atomicAdd(&g_sum, s);
    }
}

// ======================= host =======================
extern "C" void kernel_launch(void* const* d_in, const int* in_sizes, int n_in,
                              void* d_out, int out_size)
{
    const float* node_emb = (const float*)d_in[0];
    const float* edge_fea = (const float*)d_in[1];
    const float* noise    = (const float*)d_in[2];

    const int* src; const int* dst; int base;
    if (in_sizes[3] == in_sizes[2]) { src = (const int*)d_in[3];  dst = (const int*)d_in[4];  base = 5; }
    else                            { src = (const int*)d_in[15]; dst = (const int*)d_in[16]; base = 3; }

    const float* w_src1 = (const float*)d_in[base + 0];
    const float* b_src1 = (const float*)d_in[base + 1];
    const float* w_src2 = (const float*)d_in[base + 2];
    const float* b_src2 = (const float*)d_in[base + 3];
    const float* w_dst1 = (const float*)d_in[base + 4];
    const float* b_dst1 = (const float*)d_in[base + 5];
    const float* w_dst2 = (const float*)d_in[base + 6];
    const float* b_dst2 = (const float*)d_in[base + 7];
    const float* w_edge1 = (const float*)d_in[base + 8];
    const float* b_edge1 = (const float*)d_in[base + 9];
    const float* w_edge2 = (const float*)d_in[base + 10];
    const float* b_edge2 = (const float*)d_in[base + 11];

    const int Hd = in_sizes[base + 1];            // 128
    const int D  = in_sizes[base + 0] / Hd;       // 256
    const int N  = in_sizes[0] / D;               // 50000
    const int E  = in_sizes[2];                   // 1600000
    (void)n_in;

    float* out = (float*)d_out;
    float* aug = (out_size > E) ? (out + 1) : out;

    cudaFuncSetAttribute(node_tc, cudaFuncAttributeMaxDynamicSharedMemorySize, NODE_SMEM);
    cudaFuncSetAttribute(edge_tc, cudaFuncAttributeMaxDynamicSharedMemorySize, EDGE_SMEM);

    zero_kernel<<<1, 1>>>();

    int nTiles = (N + 127) / 128;
    dim3 ngrid(nTiles < 148 ? nTiles : 148, 2);
    node_tc<<<ngrid, 512, NODE_SMEM>>>(node_emb, N,
        w_src1, b_src1, w_src2, b_src2,
        w_dst1, b_dst1, w_dst2, b_dst2);

    int eTiles = (E + 63) / 64;
    int egrid = eTiles < 444 ? eTiles : 444;
    edge_tc<<<egrid, 256, EDGE_SMEM>>>(edge_fea, E,
        w_edge1, b_edge1, w_edge2, b_edge2,
        noise, src, dst, aug);

    if (out_size > E)
        finalize_kernel<<<1, 1>>>(out, 1.f / (float)E);
}

// round 10
// speedup vs baseline: 1.6725x; 1.6725x over previous
#include <cuda_runtime.h>
#include <cuda_bf16.h>
#include <cuda_fp16.h>
#include <stdint.h>
#include <math.h>

#define NMAX 50048

__device__ float g_ws[NMAX];
__device__ float g_wd[NMAX];
__device__ float g_sum;

__global__ void zero_kernel() { g_sum = 0.f; }
__global__ void finalize_kernel(float* out0, float invE) { *out0 = 1.f - g_sum * invE; }

__device__ __forceinline__ uint32_t smem_u32(const void* p) {
    uint32_t a;
    asm("{ .reg .u64 t; cvta.to.shared.u64 t, %1; cvt.u32.u64 %0, t; }" : "=r"(a) : "l"(p));
    return a;
}

__device__ __forceinline__ void ldsm4(uint32_t* r, uint32_t addr) {
    asm volatile("ldmatrix.sync.aligned.m8n8.x4.shared.b16 {%0,%1,%2,%3}, [%4];"
        : "=r"(r[0]), "=r"(r[1]), "=r"(r[2]), "=r"(r[3]) : "r"(addr) : "memory");
}

__device__ __forceinline__ void mma_f16(float* c, const uint32_t* a, uint32_t b0, uint32_t b1) {
    asm volatile(
        "mma.sync.aligned.m16n8k16.row.col.f32.f16.f16.f32 "
        "{%0,%1,%2,%3}, {%4,%5,%6,%7}, {%8,%9}, {%0,%1,%2,%3};\n"
        : "+f"(c[0]), "+f"(c[1]), "+f"(c[2]), "+f"(c[3])
        : "r"(a[0]), "r"(a[1]), "r"(a[2]), "r"(a[3]), "r"(b0), "r"(b1));
}

// -------- node k-step: fp16 2-pass (Ah·Bh + Ah·Bl), B split exact --------
__device__ __forceinline__ void k_step_n2(float (&c)[2][4][4],
    uint32_t aHi, uint32_t bHi, uint32_t bLo, int bNpStride)
{
    uint32_t ah[2][4], bh[2][4], bl[2][4];
    ldsm4(ah[0], aHi);  ldsm4(ah[1], aHi + 4352);
    ldsm4(bh[0], bHi);  ldsm4(bh[1], bHi + bNpStride);
    ldsm4(bl[0], bLo);  ldsm4(bl[1], bLo + bNpStride);
    #pragma unroll
    for (int mt = 0; mt < 2; ++mt)
        #pragma unroll
        for (int np = 0; np < 2; ++np)
            #pragma unroll
            for (int s = 0; s < 2; ++s)
                mma_f16(c[mt][np * 2 + s], ah[mt], bh[np][2 * s], bh[np][2 * s + 1]);
    #pragma unroll
    for (int mt = 0; mt < 2; ++mt)
        #pragma unroll
        for (int np = 0; np < 2; ++np)
            #pragma unroll
            for (int s = 0; s < 2; ++s)
                mma_f16(c[mt][np * 2 + s], ah[mt], bl[np][2 * s], bl[np][2 * s + 1]);
}

// ---------------- smem layouts ----------------
// Edge (256 thr, warp-autonomous): BT 0..34816, 8 warp slabs 34816+wid*4352, B1 69632, W2 70144
#define E_BT  0
#define E_A   34816
#define E_B1  69632
#define E_W2  70144
#define EDGE_SMEM 70656

// Node (R7 layout, fp16 2-pass)
#define N_BTH 0
#define N_BTL 67584
#define N_A   135168
#define N_B1  169984
#define N_W2  170496
#define N_RED 171008
#define NODE_SMEM 172544

// ======================= NODE MLPs (fp16 2-pass, R7 exact) =======================
__global__ void __launch_bounds__(512, 1)
node_tc(const float* __restrict__ X, int N,
        const float* __restrict__ Ws1, const float* __restrict__ bs1,
        const float* __restrict__ ws2, const float* __restrict__ bs2,
        const float* __restrict__ Wd1, const float* __restrict__ bd1,
        const float* __restrict__ wd2, const float* __restrict__ bd2)
{
    extern __shared__ char smem[];
    const uint32_t sb = smem_u32(smem);
    const int tid = threadIdx.x;
    const int wid = tid >> 5, lane = tid & 31;
    const int warp_m = (wid >> 2) * 32, warp_n = (wid & 3) * 32;
    const int nwid = wid & 3;

    const float* W1  = blockIdx.y ? Wd1 : Ws1;
    const float* b1g = blockIdx.y ? bd1 : bs1;
    const float* w2g = blockIdx.y ? wd2 : ws2;
    const float* b2g = blockIdx.y ? bd2 : bs2;
    float* outp = blockIdx.y ? g_wd : g_ws;

    float* sB1 = (float*)(smem + N_B1);
    float* sW2 = (float*)(smem + N_W2);
    float* sRed = (float*)(smem + N_RED);

    for (int idx = tid; idx < 256 * 128; idx += 512) {
        int n = idx & 127, k = idx >> 7;
        float w = W1[idx];
        __half h = __float2half_rn(w);
        float r = w - __half2float(h);
        int byte = n * 528 + k * 2;
        *(__half*)(smem + N_BTH + byte) = h;
        *(__half*)(smem + N_BTL + byte) = __float2half_rn(r);
    }
    if (tid < 128) { sB1[tid] = b1g[tid]; sW2[tid] = w2g[tid]; }
    const float b2v = b2g[0];
    __syncthreads();

    const uint32_t aLaneOff = (uint32_t)((warp_m + (lane & 15)) * 272 + (lane >> 4) * 16);
    const uint32_t bLaneRow = (uint32_t)(warp_n + (lane & 7) + ((lane >> 4) << 3));
    const uint32_t bLaneOff = bLaneRow * 528 + (((uint32_t)lane >> 3) & 1) * 16;

    const int numTiles = (N + 127) >> 7;
    for (int tile = blockIdx.x; tile < numTiles; tile += gridDim.x) {
        float c[2][4][4];
        #pragma unroll
        for (int i = 0; i < 2; i++)
            #pragma unroll
            for (int j = 0; j < 4; j++)
                #pragma unroll
                for (int q = 0; q < 4; q++) c[i][j][q] = 0.f;

        int row = tile * 128 + (tid >> 2);
        if (row >= N) row = N - 1;
        const float4* xp = (const float4*)(X + (size_t)row * 256);
        const int q = tid & 3;
        const int myrow = tid >> 2;

        for (int kc = 0; kc < 2; ++kc) {
            __syncthreads();
            #pragma unroll
            for (int i = 0; i < 8; ++i) {
                float4 v = xp[kc * 32 + q * 8 + i];
                __half2 h0 = __floats2half2_rn(v.x, v.y);
                __half2 h1 = __floats2half2_rn(v.z, v.w);
                int byte = myrow * 272 + (q * 32 + i * 4) * 2;
                *(uint2*)(smem + N_A + byte) = make_uint2(*(uint32_t*)&h0, *(uint32_t*)&h1);
            }
            __syncthreads();
            const uint32_t aHi = sb + N_A + aLaneOff;
            const uint32_t bHi = sb + N_BTH + bLaneOff + kc * 256;
            const uint32_t bLo = sb + N_BTL + bLaneOff + kc * 256;
            #pragma unroll
            for (int kt = 0; kt < 8; ++kt)
                k_step_n2(c, aHi + kt * 32, bHi + kt * 32, bLo + kt * 32, 16 * 528);
        }

        float part[2][2] = {{0.f, 0.f}, {0.f, 0.f}};
        #pragma unroll
        for (int mt = 0; mt < 2; ++mt)
            #pragma unroll
            for (int nt = 0; nt < 4; ++nt) {
                int n0 = warp_n + nt * 8 + (lane & 3) * 2;
                float b1a = sB1[n0], b1b = sB1[n0 + 1];
                float w2a = sW2[n0], w2b = sW2[n0 + 1];
                #pragma unroll
                for (int half = 0; half < 2; ++half) {
                    float h0 = c[mt][nt][half * 2] + b1a;     h0 = h0 > 0.f ? h0 : 0.01f * h0;
                    float h1 = c[mt][nt][half * 2 + 1] + b1b; h1 = h1 > 0.f ? h1 : 0.01f * h1;
                    part[mt][half] += h0 * w2a + h1 * w2b;
                }
            }
        #pragma unroll
        for (int mt = 0; mt < 2; ++mt)
            #pragma unroll
            for (int half = 0; half < 2; ++half) {
                part[mt][half] += __shfl_xor_sync(0xFFFFFFFFu, part[mt][half], 1);
                part[mt][half] += __shfl_xor_sync(0xFFFFFFFFu, part[mt][half], 2);
            }
        if (nwid && (lane & 3) == 0) {
            #pragma unroll
            for (int mt = 0; mt < 2; ++mt)
                #pragma unroll
                for (int half = 0; half < 2; ++half) {
                    int m = warp_m + mt * 16 + half * 8 + (lane >> 2);
                    sRed[(nwid - 1) * 128 + m] = part[mt][half];
                }
        }
        __syncthreads();
        if (nwid == 0 && (lane & 3) == 0) {
            #pragma unroll
            for (int mt = 0; mt < 2; ++mt)
                #pragma unroll
                for (int half = 0; half < 2; ++half) {
                    int m = warp_m + mt * 16 + half * 8 + (lane >> 2);
                    int nidx = tile * 128 + m;
                    if (nidx < N)
                        outp[nidx] = part[mt][half] + sRed[m] + sRed[128 + m] + sRed[256 + m] + b2v;
                }
        }
        __syncthreads();
    }
}

// ======================= EDGE MLP (warp-autonomous, no block barriers) =======================
__global__ void __launch_bounds__(256, 2)
edge_tc(const float* __restrict__ X, int E,
        const float* __restrict__ W1, const float* __restrict__ b1g,
        const float* __restrict__ w2g, const float* __restrict__ b2g,
        const float* __restrict__ noise, const int* __restrict__ src,
        const int* __restrict__ dst, float* __restrict__ aug)
{
    extern __shared__ char smem[];
    const uint32_t sb = smem_u32(smem);
    const int tid = threadIdx.x;
    const int wid = tid >> 5, lane = tid & 31;
    const bool leader = (lane & 3) == 0;

    float* sB1 = (float*)(smem + E_B1);
    float* sW2 = (float*)(smem + E_W2);

    // Bt[n][k] fp16 (hi only), stride 272. W1 is [K=128][N=128].
    for (int idx = tid; idx < 128 * 128; idx += 256) {
        int n = idx & 127, k = idx >> 7;
        *(__half*)(smem + E_BT + n * 272 + k * 2) = __float2half_rn(W1[idx]);
    }
    if (tid < 128) { sB1[tid] = b1g[tid]; sW2[tid] = w2g[tid]; }
    const float b2v = b2g[0];
    __syncthreads();   // only barrier: B/biases ready

    const uint32_t slab = sb + E_A + wid * 4352;
    const uint32_t aBase = slab + (lane & 15) * 272 + (lane >> 4) * 16;
    const uint32_t bBase = sb + E_BT + ((lane & 7) + ((lane >> 4) << 3)) * 272
                         + (((uint32_t)lane >> 3) & 1) * 16;

    const int numTiles = (E + 15) >> 4;   // 16-edge warp tiles
    const int gWarp = blockIdx.x * 8 + wid;
    const int wStride = gridDim.x * 8;
    float localSum = 0.f;

    for (int t = gWarp; t < numTiles; t += wStride) {
        const int e0 = t * 16;

        // leaders prefetch gather operands for their 2 edges (hidden under load/MMA)
        float gwA = 0.f, gwB = 0.f, nzA = 0.5f, nzB = 0.5f;
        int eA = -1, eB = -1;
        if (leader) {
            int r = lane >> 2;
            int a = e0 + r, bI = e0 + r + 8;
            if (a < E) {
                eA = a;
                gwA = g_ws[__ldg(&src[a])] + g_wd[__ldg(&dst[a])];
                nzA = __ldg(&noise[a]);
            }
            if (bI < E) {
                eB = bI;
                gwB = g_ws[__ldg(&src[bI])] + g_wd[__ldg(&dst[bI])];
                nzB = __ldg(&noise[bI]);
            }
        }

        // load 16 edges x 128 floats, perfectly coalesced; cvt; STS.64 conflict-free
        #pragma unroll
        for (int k = 0; k < 16; ++k) {
            int row = e0 + k;
            if (row >= E) row = E - 1;
            float4 v = __ldg((const float4*)(X + (size_t)row * 128) + lane);
            __half2 h0 = __floats2half2_rn(v.x, v.y);
            __half2 h1 = __floats2half2_rn(v.z, v.w);
            *(uint2*)((char*)smem + E_A + wid * 4352 + k * 272 + lane * 8)
                = make_uint2(*(uint32_t*)&h0, *(uint32_t*)&h1);
        }
        __syncwarp();

        // MMA: 16 rows x 128 cols, K=128
        float c[8][2][4];
        #pragma unroll
        for (int g = 0; g < 8; ++g)
            #pragma unroll
            for (int s = 0; s < 2; ++s)
                #pragma unroll
                for (int q = 0; q < 4; ++q) c[g][s][q] = 0.f;

        #pragma unroll
        for (int kt = 0; kt < 8; ++kt) {
            uint32_t a[4];
            ldsm4(a, aBase + kt * 32);
            #pragma unroll
            for (int g = 0; g < 8; ++g) {
                uint32_t bb[4];
                ldsm4(bb, bBase + g * (16 * 272) + kt * 32);
                mma_f16(c[g][0], a, bb[0], bb[1]);
                mma_f16(c[g][1], a, bb[2], bb[3]);
            }
        }

        // warp-local epilogue: bias + LeakyReLU + w2 dot
        float pA = 0.f, pB = 0.f;
        #pragma unroll
        for (int g = 0; g < 8; ++g)
            #pragma unroll
            for (int s = 0; s < 2; ++s) {
                int n0 = g * 16 + s * 8 + (lane & 3) * 2;
                float2 b1 = *(float2*)(sB1 + n0);
                float2 w2 = *(float2*)(sW2 + n0);
                float h0 = c[g][s][0] + b1.x; h0 = h0 > 0.f ? h0 : 0.01f * h0;
                float h1 = c[g][s][1] + b1.y; h1 = h1 > 0.f ? h1 : 0.01f * h1;
                pA += h0 * w2.x + h1 * w2.y;
                float h2 = c[g][s][2] + b1.x; h2 = h2 > 0.f ? h2 : 0.01f * h2;
                float h3 = c[g][s][3] + b1.y; h3 = h3 > 0.f ? h3 : 0.01f * h3;
                pB += h2 * w2.x + h3 * w2.y;
            }
        pA += __shfl_xor_sync(0xFFFFFFFFu, pA, 1);
        pA += __shfl_xor_sync(0xFFFFFFFFu, pA, 2);
        pB += __shfl_xor_sync(0xFFFFFFFFu, pB, 1);
        pB += __shfl_xor_sync(0xFFFFFFFFu, pB, 2);

        if (leader) {
            if (eA >= 0) {
                float weight = pA + b2v + gwA;
                float eps = fmaf(2e-4f - 1.f, nzA, 1.f - 1e-4f);
                float gate = (logf(eps) - log1pf(-eps) + weight) * 2.f;
                float a = 1.f / (1.f + expf(-gate));
                aug[eA] = a;
                localSum += a;
            }
            if (eB >= 0) {
                float weight = pB + b2v + gwB;
                float eps = fmaf(2e-4f - 1.f, nzB, 1.f - 1e-4f);
                float gate = (logf(eps) - log1pf(-eps) + weight) * 2.f;
                float a = 1.f / (1.f + expf(-gate));
                aug[eB] = a;
                localSum += a;
            }
        }
    }

    // block reduce localSum (one barrier at the very end)
    #pragma unroll
    for (int o = 16; o > 0; o >>= 1)
        localSum += __shfl_xor_sync(0xFFFFFFFFu, localSum, o);
    __shared__ float sPart[8];
    if (lane == 0) sPart[wid] = localSum;
    __syncthreads();
    if (tid == 0) {
        float s = 0.f;
        #pragma unroll
        for (int i = 0; i < 8; i++) s += sPart[i];
        atomicAdd(&g_sum, s);
    }
}

// ======================= host =======================
extern "C" void kernel_launch(void* const* d_in, const int* in_sizes, int n_in,
                              void* d_out, int out_size)
{
    const float* node_emb = (const float*)d_in[0];
    const float* edge_fea = (const float*)d_in[1];
    const float* noise    = (const float*)d_in[2];

    const int* src; const int* dst; int base;
    if (in_sizes[3] == in_sizes[2]) { src = (const int*)d_in[3];  dst = (const int*)d_in[4];  base = 5; }
    else                            { src = (const int*)d_in[15]; dst = (const int*)d_in[16]; base = 3; }

    const float* w_src1 = (const float*)d_in[base + 0];
    const float* b_src1 = (const float*)d_in[base + 1];
    const float* w_src2 = (const float*)d_in[base + 2];
    const float* b_src2 = (const float*)d_in[base + 3];
    const float* w_dst1 = (const float*)d_in[base + 4];
    const float* b_dst1 = (const float*)d_in[base + 5];
    const float* w_dst2 = (const float*)d_in[base + 6];
    const float* b_dst2 = (const float*)d_in[base + 7];
    const float* w_edge1 = (const float*)d_in[base + 8];
    const float* b_edge1 = (const float*)d_in[base + 9];
    const float* w_edge2 = (const float*)d_in[base + 10];
    const float* b_edge2 = (const float*)d_in[base + 11];

    const int Hd = in_sizes[base + 1];            // 128
    const int D  = in_sizes[base + 0] / Hd;       // 256
    const int N  = in_sizes[0] / D;               // 50000
    const int E  = in_sizes[2];                   // 1600000
    (void)n_in;

    float* out = (float*)d_out;
    float* aug = (out_size > E) ? (out + 1) : out;

    cudaFuncSetAttribute(node_tc, cudaFuncAttributeMaxDynamicSharedMemorySize, NODE_SMEM);
    cudaFuncSetAttribute(edge_tc, cudaFuncAttributeMaxDynamicSharedMemorySize, EDGE_SMEM);

    zero_kernel<<<1, 1>>>();

    int nTiles = (N + 127) / 128;
    dim3 ngrid(nTiles < 148 ? nTiles : 148, 2);
    node_tc<<<ngrid, 512, NODE_SMEM>>>(node_emb, N,
        w_src1, b_src1, w_src2, b_src2,
        w_dst1, b_dst1, w_dst2, b_dst2);

    int eWarpTiles = (E + 15) / 16;
    int egrid = (eWarpTiles + 7) / 8;
    if (egrid > 296) egrid = 296;
    edge_tc<<<egrid, 256, EDGE_SMEM>>>(edge_fea, E,
        w_edge1, b_edge1, w_edge2, b_edge2,
        noise, src, dst, aug);

    if (out_size > E)
        finalize_kernel<<<1, 1>>>(out, 1.f / (float)E);
}

// round 11
// speedup vs baseline: 1.8729x; 1.1198x over previous
#include <cuda_runtime.h>
#include <cuda_bf16.h>
#include <cuda_fp16.h>
#include <stdint.h>
#include <math.h>

#define NMAX 50048

__device__ float g_ws[NMAX];
__device__ float g_wd[NMAX];
__device__ float g_sum;

__global__ void zero_kernel() { g_sum = 0.f; }
__global__ void finalize_kernel(float* out0, float invE) { *out0 = 1.f - g_sum * invE; }

__device__ __forceinline__ uint32_t smem_u32(const void* p) {
    uint32_t a;
    asm("{ .reg .u64 t; cvta.to.shared.u64 t, %1; cvt.u32.u64 %0, t; }" : "=r"(a) : "l"(p));
    return a;
}

__device__ __forceinline__ void ldsm4(uint32_t* r, uint32_t addr) {
    asm volatile("ldmatrix.sync.aligned.m8n8.x4.shared.b16 {%0,%1,%2,%3}, [%4];"
        : "=r"(r[0]), "=r"(r[1]), "=r"(r[2]), "=r"(r[3]) : "r"(addr) : "memory");
}

__device__ __forceinline__ void mma_f16(float* c, const uint32_t* a, uint32_t b0, uint32_t b1) {
    asm volatile(
        "mma.sync.aligned.m16n8k16.row.col.f32.f16.f16.f32 "
        "{%0,%1,%2,%3}, {%4,%5,%6,%7}, {%8,%9}, {%0,%1,%2,%3};\n"
        : "+f"(c[0]), "+f"(c[1]), "+f"(c[2]), "+f"(c[3])
        : "r"(a[0]), "r"(a[1]), "r"(a[2]), "r"(a[3]), "r"(b0), "r"(b1));
}

// ---------------- smem layouts ----------------
// Edge (256 thr, warp-autonomous): BT 0..34816, 8 warp slabs, B1, W2
#define E_BT  0
#define E_A   34816
#define E_B1  69632
#define E_W2  70144
#define EDGE_SMEM 70656

// Node (256 thr, warp-autonomous, K=256 single-pass fp16 B): BT [128][528B], 8 slabs, biases
#define NB_BT  0
#define NB_A   67584
#define NB_B1  102400
#define NB_W2  102912
#define NODE_SMEM 103424

// ======================= NODE MLPs (warp-autonomous, fp16 single-pass) =======================
__global__ void __launch_bounds__(256, 2)
node_tc(const float* __restrict__ X, int N,
        const float* __restrict__ Ws1, const float* __restrict__ bs1,
        const float* __restrict__ ws2, const float* __restrict__ bs2,
        const float* __restrict__ Wd1, const float* __restrict__ bd1,
        const float* __restrict__ wd2, const float* __restrict__ bd2)
{
    extern __shared__ char smem[];
    const uint32_t sb = smem_u32(smem);
    const int tid = threadIdx.x;
    const int wid = tid >> 5, lane = tid & 31;
    const bool leader = (lane & 3) == 0;

    const float* W1  = blockIdx.y ? Wd1 : Ws1;
    const float* b1g = blockIdx.y ? bd1 : bs1;
    const float* w2g = blockIdx.y ? wd2 : ws2;
    const float* b2g = blockIdx.y ? bd2 : bs2;
    float* outp = blockIdx.y ? g_wd : g_ws;

    float* sB1 = (float*)(smem + NB_B1);
    float* sW2 = (float*)(smem + NB_W2);

    // Bt[n][k] fp16 (hi only), stride 528. W1 is [K=256][N=128].
    for (int idx = tid; idx < 256 * 128; idx += 256) {
        int n = idx & 127, k = idx >> 7;
        *(__half*)(smem + NB_BT + n * 528 + k * 2) = __float2half_rn(W1[idx]);
    }
    if (tid < 128) { sB1[tid] = b1g[tid]; sW2[tid] = w2g[tid]; }
    const float b2v = b2g[0];
    __syncthreads();   // only block barrier: B/biases ready

    const uint32_t aBase = sb + NB_A + wid * 4352 + (lane & 15) * 272 + (lane >> 4) * 16;
    const uint32_t bBase = sb + NB_BT + ((lane & 7) + ((lane >> 4) << 3)) * 528
                         + (((uint32_t)lane >> 3) & 1) * 16;

    const int numTiles = (N + 15) >> 4;
    const int gWarp = blockIdx.x * 8 + wid;
    const int wStride = gridDim.x * 8;

    for (int t = gWarp; t < numTiles; t += wStride) {
        const int n0 = t * 16;

        float c[8][2][4];
        #pragma unroll
        for (int g = 0; g < 8; ++g)
            #pragma unroll
            for (int s = 0; s < 2; ++s)
                #pragma unroll
                for (int q = 0; q < 4; ++q) c[g][s][q] = 0.f;

        #pragma unroll
        for (int kc = 0; kc < 2; ++kc) {
            // load 16 rows x 128 floats (this K chunk), cvt, STS
            #pragma unroll
            for (int k = 0; k < 16; ++k) {
                int row = n0 + k;
                if (row >= N) row = N - 1;
                float4 v = __ldg((const float4*)(X + (size_t)row * 256 + kc * 128) + lane);
                __half2 h0 = __floats2half2_rn(v.x, v.y);
                __half2 h1 = __floats2half2_rn(v.z, v.w);
                *(uint2*)((char*)smem + NB_A + wid * 4352 + k * 272 + lane * 8)
                    = make_uint2(*(uint32_t*)&h0, *(uint32_t*)&h1);
            }
            __syncwarp();

            #pragma unroll
            for (int kt = 0; kt < 8; ++kt) {
                uint32_t a[4];
                ldsm4(a, aBase + kt * 32);
                #pragma unroll
                for (int g = 0; g < 8; ++g) {
                    uint32_t bb[4];
                    ldsm4(bb, bBase + kc * 256 + g * (16 * 528) + kt * 32);
                    mma_f16(c[g][0], a, bb[0], bb[1]);
                    mma_f16(c[g][1], a, bb[2], bb[3]);
                }
            }
            __syncwarp();   // slab reuse safety before next kc STS
        }

        // warp-local epilogue
        float pA = 0.f, pB = 0.f;
        #pragma unroll
        for (int g = 0; g < 8; ++g)
            #pragma unroll
            for (int s = 0; s < 2; ++s) {
                int nn = g * 16 + s * 8 + (lane & 3) * 2;
                float2 b1 = *(float2*)(sB1 + nn);
                float2 w2 = *(float2*)(sW2 + nn);
                float h0 = c[g][s][0] + b1.x; h0 = h0 > 0.f ? h0 : 0.01f * h0;
                float h1 = c[g][s][1] + b1.y; h1 = h1 > 0.f ? h1 : 0.01f * h1;
                pA += h0 * w2.x + h1 * w2.y;
                float h2 = c[g][s][2] + b1.x; h2 = h2 > 0.f ? h2 : 0.01f * h2;
                float h3 = c[g][s][3] + b1.y; h3 = h3 > 0.f ? h3 : 0.01f * h3;
                pB += h2 * w2.x + h3 * w2.y;
            }
        pA += __shfl_xor_sync(0xFFFFFFFFu, pA, 1);
        pA += __shfl_xor_sync(0xFFFFFFFFu, pA, 2);
        pB += __shfl_xor_sync(0xFFFFFFFFu, pB, 1);
        pB += __shfl_xor_sync(0xFFFFFFFFu, pB, 2);

        if (leader) {
            int r = lane >> 2;
            int a = n0 + r, bI = n0 + r + 8;
            if (a < N) outp[a] = pA + b2v;
            if (bI < N) outp[bI] = pB + b2v;
        }
    }
}

// ======================= EDGE MLP (warp-autonomous — R10 champion, unchanged) =======================
__global__ void __launch_bounds__(256, 2)
edge_tc(const float* __restrict__ X, int E,
        const float* __restrict__ W1, const float* __restrict__ b1g,
        const float* __restrict__ w2g, const float* __restrict__ b2g,
        const float* __restrict__ noise, const int* __restrict__ src,
        const int* __restrict__ dst, float* __restrict__ aug)
{
    extern __shared__ char smem[];
    const uint32_t sb = smem_u32(smem);
    const int tid = threadIdx.x;
    const int wid = tid >> 5, lane = tid & 31;
    const bool leader = (lane & 3) == 0;

    float* sB1 = (float*)(smem + E_B1);
    float* sW2 = (float*)(smem + E_W2);

    for (int idx = tid; idx < 128 * 128; idx += 256) {
        int n = idx & 127, k = idx >> 7;
        *(__half*)(smem + E_BT + n * 272 + k * 2) = __float2half_rn(W1[idx]);
    }
    if (tid < 128) { sB1[tid] = b1g[tid]; sW2[tid] = w2g[tid]; }
    const float b2v = b2g[0];
    __syncthreads();

    const uint32_t aBase = sb + E_A + wid * 4352 + (lane & 15) * 272 + (lane >> 4) * 16;
    const uint32_t bBase = sb + E_BT + ((lane & 7) + ((lane >> 4) << 3)) * 272
                         + (((uint32_t)lane >> 3) & 1) * 16;

    const int numTiles = (E + 15) >> 4;
    const int gWarp = blockIdx.x * 8 + wid;
    const int wStride = gridDim.x * 8;
    float localSum = 0.f;

    for (int t = gWarp; t < numTiles; t += wStride) {
        const int e0 = t * 16;

        float gwA = 0.f, gwB = 0.f, nzA = 0.5f, nzB = 0.5f;
        int eA = -1, eB = -1;
        if (leader) {
            int r = lane >> 2;
            int a = e0 + r, bI = e0 + r + 8;
            if (a < E) {
                eA = a;
                gwA = g_ws[__ldg(&src[a])] + g_wd[__ldg(&dst[a])];
                nzA = __ldg(&noise[a]);
            }
            if (bI < E) {
                eB = bI;
                gwB = g_ws[__ldg(&src[bI])] + g_wd[__ldg(&dst[bI])];
                nzB = __ldg(&noise[bI]);
            }
        }

        #pragma unroll
        for (int k = 0; k < 16; ++k) {
            int row = e0 + k;
            if (row >= E) row = E - 1;
            float4 v = __ldg((const float4*)(X + (size_t)row * 128) + lane);
            __half2 h0 = __floats2half2_rn(v.x, v.y);
            __half2 h1 = __floats2half2_rn(v.z, v.w);
            *(uint2*)((char*)smem + E_A + wid * 4352 + k * 272 + lane * 8)
                = make_uint2(*(uint32_t*)&h0, *(uint32_t*)&h1);
        }
        __syncwarp();

        float c[8][2][4];
        #pragma unroll
        for (int g = 0; g < 8; ++g)
            #pragma unroll
            for (int s = 0; s < 2; ++s)
                #pragma unroll
                for (int q = 0; q < 4; ++q) c[g][s][q] = 0.f;

        #pragma unroll
        for (int kt = 0; kt < 8; ++kt) {
            uint32_t a[4];
            ldsm4(a, aBase + kt * 32);
            #pragma unroll
            for (int g = 0; g < 8; ++g) {
                uint32_t bb[4];
                ldsm4(bb, bBase + g * (16 * 272) + kt * 32);
                mma_f16(c[g][0], a, bb[0], bb[1]);
                mma_f16(c[g][1], a, bb[2], bb[3]);
            }
        }

        float pA = 0.f, pB = 0.f;
        #pragma unroll
        for (int g = 0; g < 8; ++g)
            #pragma unroll
            for (int s = 0; s < 2; ++s) {
                int n0 = g * 16 + s * 8 + (lane & 3) * 2;
                float2 b1 = *(float2*)(sB1 + n0);
                float2 w2 = *(float2*)(sW2 + n0);
                float h0 = c[g][s][0] + b1.x; h0 = h0 > 0.f ? h0 : 0.01f * h0;
                float h1 = c[g][s][1] + b1.y; h1 = h1 > 0.f ? h1 : 0.01f * h1;
                pA += h0 * w2.x + h1 * w2.y;
                float h2 = c[g][s][2] + b1.x; h2 = h2 > 0.f ? h2 : 0.01f * h2;
                float h3 = c[g][s][3] + b1.y; h3 = h3 > 0.f ? h3 : 0.01f * h3;
                pB += h2 * w2.x + h3 * w2.y;
            }
        pA += __shfl_xor_sync(0xFFFFFFFFu, pA, 1);
        pA += __shfl_xor_sync(0xFFFFFFFFu, pA, 2);
        pB += __shfl_xor_sync(0xFFFFFFFFu, pB, 1);
        pB += __shfl_xor_sync(0xFFFFFFFFu, pB, 2);

        if (leader) {
            if (eA >= 0) {
                float weight = pA + b2v + gwA;
                float eps = fmaf(2e-4f - 1.f, nzA, 1.f - 1e-4f);
                float gate = (logf(eps) - log1pf(-eps) + weight) * 2.f;
                float a = 1.f / (1.f + expf(-gate));
                aug[eA] = a;
                localSum += a;
            }
            if (eB >= 0) {
                float weight = pB + b2v + gwB;
                float eps = fmaf(2e-4f - 1.f, nzB, 1.f - 1e-4f);
                float gate = (logf(eps) - log1pf(-eps) + weight) * 2.f;
                float a = 1.f / (1.f + expf(-gate));
                aug[eB] = a;
                localSum += a;
            }
        }
    }

    #pragma unroll
    for (int o = 16; o > 0; o >>= 1)
        localSum += __shfl_xor_sync(0xFFFFFFFFu, localSum, o);
    __shared__ float sPart[8];
    if (lane == 0) sPart[wid] = localSum;
    __syncthreads();
    if (tid == 0) {
        float s = 0.f;
        #pragma unroll
        for (int i = 0; i < 8; i++) s += sPart[i];
        atomicAdd(&g_sum, s);
    }
}

// ======================= host =======================
extern "C" void kernel_launch(void* const* d_in, const int* in_sizes, int n_in,
                              void* d_out, int out_size)
{
    const float* node_emb = (const float*)d_in[0];
    const float* edge_fea = (const float*)d_in[1];
    const float* noise    = (const float*)d_in[2];

    const int* src; const int* dst; int base;
    if (in_sizes[3] == in_sizes[2]) { src = (const int*)d_in[3];  dst = (const int*)d_in[4];  base = 5; }
    else                            { src = (const int*)d_in[15]; dst = (const int*)d_in[16]; base = 3; }

    const float* w_src1 = (const float*)d_in[base + 0];
    const float* b_src1 = (const float*)d_in[base + 1];
    const float* w_src2 = (const float*)d_in[base + 2];
    const float* b_src2 = (const float*)d_in[base + 3];
    const float* w_dst1 = (const float*)d_in[base + 4];
    const float* b_dst1 = (const float*)d_in[base + 5];
    const float* w_dst2 = (const float*)d_in[base + 6];
    const float* b_dst2 = (const float*)d_in[base + 7];
    const float* w_edge1 = (const float*)d_in[base + 8];
    const float* b_edge1 = (const float*)d_in[base + 9];
    const float* w_edge2 = (const float*)d_in[base + 10];
    const float* b_edge2 = (const float*)d_in[base + 11];

    const int Hd = in_sizes[base + 1];            // 128
    const int D  = in_sizes[base + 0] / Hd;       // 256
    const int N  = in_sizes[0] / D;               // 50000
    const int E  = in_sizes[2];                   // 1600000
    (void)n_in;

    float* out = (float*)d_out;
    float* aug = (out_size > E) ? (out + 1) : out;

    cudaFuncSetAttribute(node_tc, cudaFuncAttributeMaxDynamicSharedMemorySize, NODE_SMEM);
    cudaFuncSetAttribute(edge_tc, cudaFuncAttributeMaxDynamicSharedMemorySize, EDGE_SMEM);

    zero_kernel<<<1, 1>>>();

    int nWarpTiles = (N + 15) / 16;
    int ngx = (nWarpTiles + 7) / 8;
    if (ngx > 296) ngx = 296;
    dim3 ngrid(ngx, 2);
    node_tc<<<ngrid, 256, NODE_SMEM>>>(node_emb, N,
        w_src1, b_src1, w_src2, b_src2,
        w_dst1, b_dst1, w_dst2, b_dst2);

    int eWarpTiles = (E + 15) / 16;
    int egrid = (eWarpTiles + 7) / 8;
    if (egrid > 296) egrid = 296;
    edge_tc<<<egrid, 256, EDGE_SMEM>>>(edge_fea, E,
        w_edge1, b_edge1, w_edge2, b_edge2,
        noise, src, dst, aug);

    if (out_size > E)
        finalize_kernel<<<1, 1>>>(out, 1.f / (float)E);
}